// round 13
// baseline (speedup 1.0000x reference)
#include <cuda_runtime.h>
#include <cuda_fp16.h>
#include <mma.h>
#include <cstdint>

using namespace nvcuda;

#define NB     32
#define NC     512
#define NHEADS 8
#define ND     64
#define NSP    4096   // H*W

// Scratch (no allocations allowed)
__device__ __half g_W2[(size_t)NB * NC * NC];          // fp16 W @ blockdiag(A)
__device__ __half g_Gr[(size_t)NB * NC * NSP];         // fp16-rounded G
__device__ float  g_Sp[(size_t)NB * NHEADS * 2 * ND * ND];  // partial Gram sums
__device__ float  g_sqp[(size_t)NB * NHEADS * 2 * 128];     // partial sumsq (L|G)

// ---------------------------------------------------------------------------
// helpers
// ---------------------------------------------------------------------------
__device__ __forceinline__ uint32_t smem_u32(const void* p) {
    uint32_t a;
    asm("{ .reg .u64 t; cvta.to.shared.u64 t, %1; cvt.u32.u64 %0, t; }" : "=r"(a) : "l"(p));
    return a;
}
__device__ __forceinline__ void cp16(void* dst_smem, const void* src) {
    asm volatile("cp.async.cg.shared.global [%0], [%1], 16;"
                 :: "r"(smem_u32(dst_smem)), "l"(src));
}
#define CP_COMMIT() asm volatile("cp.async.commit_group;" ::: "memory")
#define CP_WAIT(n)  asm volatile("cp.async.wait_group %0;" :: "n"(n) : "memory")

__device__ __forceinline__ void st_h8(__half* p, float4 a, float4 b) {
    union { __half2 h[4]; uint4 u; } pk;
    pk.h[0] = __floats2half2_rn(a.x, a.y);
    pk.h[1] = __floats2half2_rn(a.z, a.w);
    pk.h[2] = __floats2half2_rn(b.x, b.y);
    pk.h[3] = __floats2half2_rn(b.z, b.w);
    *(uint4*)p = pk.u;
}

// ---------------------------------------------------------------------------
// Kernel 1a: attn_partial.  grid (2, NHEADS, NB).  Each CTA: Gram + sumsq over
// cols [half*2048, +2048) via 4-slot cp.async raw ring; fp16 tiles; fp16 WMMA;
// writes partial S (fp32) and partial sumsq to global, fp16 G to g_Gr.
// ---------------------------------------------------------------------------
#define LDA1 36
#define RSTG (64 * LDA1 * 2)     // 4608 floats per raw stage
#define LDH1 40
#define PART_DSM (4 * RSTG * 4 + 2 * 64 * LDH1 * 2 * 2)
#define NHALF 2048
#define NCHK  (NHALF / 32)       // 64 chunks

__global__ __launch_bounds__(256) void attn_partial_kernel(
    const float* __restrict__ localf,
    const float* __restrict__ globalf)
{
    extern __shared__ char dsm[];
    float*  sRaw  = (float*)dsm;                         // 4 x 4608 floats
    __half* sHalf = (__half*)(dsm + 4 * RSTG * 4);       // 2 x 5120 halfs

    const int half = blockIdx.x;
    const int h    = blockIdx.y;
    const int b    = blockIdx.z;
    const int cbase = half * NHALF;
    const float* Lp = localf  + (size_t)(b * NC + h * ND) * NSP + cbase;
    const float* Gp = globalf + (size_t)(b * NC + h * ND) * NSP + cbase;

    const int t    = threadIdx.x;
    const int warp = t >> 5;
    const int srow = t >> 2;         // 0..63
    const int scol = (t & 3) * 8;    // 0,8,16,24

    const int m0 = (warp & 1) * 32;
    const int n0 = (warp >> 1) * 16;

    wmma::fragment<wmma::accumulator, 16, 16, 16, float> acc0, acc1;
    wmma::fill_fragment(acc0, 0.0f);
    wmma::fill_fragment(acc1, 0.0f);

    float sqL = 0.f, sqG = 0.f;

    const float* lsrc = Lp + (size_t)srow * NSP + scol;
    const float* gsrc = Gp + (size_t)srow * NSP + scol;
    const int rawOff = srow * LDA1 + scol;
    __half* grout = g_Gr + ((size_t)(b * NC + h * ND) + srow) * NSP + cbase + scol;

    #pragma unroll
    for (int kc = 0; kc < 3; ++kc) {
        float* dl = sRaw + kc * RSTG + rawOff;
        float* dg = dl + 64 * LDA1;
        cp16(dl, lsrc + kc * 32); cp16(dl + 4, lsrc + kc * 32 + 4);
        cp16(dg, gsrc + kc * 32); cp16(dg + 4, gsrc + kc * 32 + 4);
        CP_COMMIT();
    }

    for (int kc = 0; kc < NCHK; ++kc) {
        // slot (kc+3)&3 == (kc-1)&3; its raw reads finished before iter kc-1's
        // second barrier, which all threads passed before entering iter kc.
        const int kn = kc + 3;
        if (kn < NCHK) {
            float* dl = sRaw + (kn & 3) * RSTG + rawOff;
            float* dg = dl + 64 * LDA1;
            cp16(dl, lsrc + kn * 32); cp16(dl + 4, lsrc + kn * 32 + 4);
            cp16(dg, gsrc + kn * 32); cp16(dg + 4, gsrc + kn * 32 + 4);
        }
        CP_COMMIT();
        CP_WAIT(3);
        __syncthreads();

        float* stg = sRaw + (kc & 3) * RSTG;
        const float4* lp4 = (const float4*)(stg + rawOff);
        const float4* gp4 = (const float4*)(stg + 64 * LDA1 + rawOff);
        float4 l0 = lp4[0], l1 = lp4[1], g0 = gp4[0], g1 = gp4[1];

        sqL += l0.x*l0.x + l0.y*l0.y + l0.z*l0.z + l0.w*l0.w
             + l1.x*l1.x + l1.y*l1.y + l1.z*l1.z + l1.w*l1.w;
        sqG += g0.x*g0.x + g0.y*g0.y + g0.z*g0.z + g0.w*g0.w
             + g1.x*g1.x + g1.y*g1.y + g1.z*g1.z + g1.w*g1.w;

        __half* sLh = sHalf + (kc & 1) * 5120;
        __half* sGh = sLh + 64 * LDH1;
        st_h8(sLh + srow * LDH1 + scol, l0, l1);
        st_h8(sGh + srow * LDH1 + scol, g0, g1);
        st_h8(grout + kc * 32, g0, g1);
        __syncthreads();

        #pragma unroll
        for (int kk = 0; kk < 32; kk += 16) {
            wmma::fragment<wmma::matrix_b, 16, 16, 16, __half, wmma::col_major> bf;
            wmma::load_matrix_sync(bf, sGh + n0 * LDH1 + kk, LDH1);
            wmma::fragment<wmma::matrix_a, 16, 16, 16, __half, wmma::row_major> af;
            wmma::load_matrix_sync(af, sLh + m0 * LDH1 + kk, LDH1);
            wmma::mma_sync(acc0, af, bf, acc0);
            wmma::load_matrix_sync(af, sLh + (m0 + 16) * LDH1 + kk, LDH1);
            wmma::mma_sync(acc1, af, bf, acc1);
        }
    }

    // write partials
    const int bh2 = (b * NHEADS + h) * 2 + half;
    sqL += __shfl_xor_sync(0xffffffffu, sqL, 1);
    sqL += __shfl_xor_sync(0xffffffffu, sqL, 2);
    sqG += __shfl_xor_sync(0xffffffffu, sqG, 1);
    sqG += __shfl_xor_sync(0xffffffffu, sqG, 2);
    if ((t & 3) == 0) {
        g_sqp[(size_t)bh2 * 128 + srow]      = sqL;
        g_sqp[(size_t)bh2 * 128 + 64 + srow] = sqG;
    }
    float* sp = g_Sp + (size_t)bh2 * ND * ND;
    wmma::store_matrix_sync(sp + m0 * ND + n0, acc0, ND, wmma::mem_row_major);
    wmma::store_matrix_sync(sp + (m0 + 16) * ND + n0, acc1, ND, wmma::mem_row_major);
}

// ---------------------------------------------------------------------------
// Kernel 1b: attn_finalize.  grid (NHEADS, NB).  S = S0+S1; fp32 softmax ->
// fp16 A; W2 slice = W[:,h*64:+64] @ A -> fp16 g_W2.  Static smem.
// ---------------------------------------------------------------------------
#define LDS1 68
#define LDSH 72

__global__ __launch_bounds__(256) void attn_finalize_kernel(
    const float* __restrict__ temp,
    const float* __restrict__ projw)
{
    __shared__ float sBuf[10880];            // 43.5 KB static
    float*  sS  = sBuf;                      // 64x68 f32        (4352 f)
    __half* sSh = (__half*)(sBuf + 4352);    // 64x72 h          (2304 f)
    __half* sWp = (__half*)(sBuf + 4352 + 2304);  // 512x16 h    (4096 f)
    float*  sInv = sBuf + 4352 + 2304 + 4096;     // 128 f

    const int h = blockIdx.x;
    const int b = blockIdx.y;
    const int t    = threadIdx.x;
    const int lane = t & 31;
    const int warp = t >> 5;

    const int bh = b * NHEADS + h;
    const float* sp0 = g_Sp + (size_t)(bh * 2)     * ND * ND;
    const float* sp1 = g_Sp + (size_t)(bh * 2 + 1) * ND * ND;

    for (int i = t; i < ND * ND; i += 256) {
        sS[(i >> 6) * LDS1 + (i & 63)] = sp0[i] + sp1[i];
    }
    if (t < 128) {
        float sq = g_sqp[(size_t)(bh * 2) * 128 + t] + g_sqp[(size_t)(bh * 2 + 1) * 128 + t];
        sInv[t] = 1.f / fmaxf(sqrtf(sq), 1e-12f);
    }
    __syncthreads();

    const float tval = temp[h];
    for (int rr = warp * 8; rr < warp * 8 + 8; ++rr) {
        float il = sInv[rr] * tval;
        float x1 = sS[rr * LDS1 + lane]      * il * sInv[64 + lane];
        float x2 = sS[rr * LDS1 + 32 + lane] * il * sInv[96 + lane];
        float mx = fmaxf(x1, x2);
        #pragma unroll
        for (int o = 16; o > 0; o >>= 1)
            mx = fmaxf(mx, __shfl_xor_sync(0xffffffffu, mx, o));
        float e1 = expf(x1 - mx);
        float e2 = expf(x2 - mx);
        float s = e1 + e2;
        #pragma unroll
        for (int o = 16; o > 0; o >>= 1)
            s += __shfl_xor_sync(0xffffffffu, s, o);
        float is = 1.f / s;
        sSh[rr * LDSH + lane]      = __float2half_rn(e1 * is);
        sSh[rr * LDSH + 32 + lane] = __float2half_rn(e2 * is);
    }
    __syncthreads();

    // Phase C: W2 slice [512 x 64] = W[:, h*64:+64] @ A
    const int o0w = warp * 64;
    const int hk  = h * ND;
    wmma::fragment<wmma::accumulator, 16, 16, 16, float> wacc[4][4];
    #pragma unroll
    for (int i = 0; i < 4; ++i)
        #pragma unroll
        for (int j = 0; j < 4; ++j)
            wmma::fill_fragment(wacc[i][j], 0.0f);

    for (int kg = 0; kg < 4; ++kg) {
        for (int idx = t; idx < 512 * 4; idx += 256) {
            const int o = idx >> 2, q = (idx & 3) * 4;
            float4 wv = *(const float4*)(projw + (size_t)o * NC + hk + kg * 16 + q);
            __half* d = sWp + o * 16 + q;
            d[0] = __float2half_rn(wv.x); d[1] = __float2half_rn(wv.y);
            d[2] = __float2half_rn(wv.z); d[3] = __float2half_rn(wv.w);
        }
        __syncthreads();

        wmma::fragment<wmma::matrix_b, 16, 16, 16, __half, wmma::row_major> bf[4];
        #pragma unroll
        for (int j = 0; j < 4; ++j)
            wmma::load_matrix_sync(bf[j], sSh + (kg * 16) * LDSH + j * 16, LDSH);
        #pragma unroll
        for (int i = 0; i < 4; ++i) {
            wmma::fragment<wmma::matrix_a, 16, 16, 16, __half, wmma::row_major> af;
            wmma::load_matrix_sync(af, sWp + (o0w + i * 16) * 16, 16);
            #pragma unroll
            for (int j = 0; j < 4; ++j)
                wmma::mma_sync(wacc[i][j], af, bf[j], wacc[i][j]);
        }
        __syncthreads();
    }

    // write W2 slice as fp16 via per-warp fp32 scratch (reuse sBuf; all prior
    // smem users are dead and fenced by the barrier above)
    float* sW = sBuf + warp * 1088;     // 16x68 slab per warp (8*1088=8704<=10880)
    __half* w2p = g_W2 + (size_t)b * NC * NC;
    const int r  = lane >> 1;
    const int c0 = (lane & 1) * 32;
    #pragma unroll
    for (int i = 0; i < 4; ++i) {
        #pragma unroll
        for (int j = 0; j < 4; ++j)
            wmma::store_matrix_sync(sW + j * 16, wacc[i][j], 68, wmma::mem_row_major);
        __syncwarp();
        __half* dst = w2p + (size_t)(o0w + i * 16 + r) * NC + hk + c0;
        #pragma unroll
        for (int q = 0; q < 4; ++q) {
            const float* s = sW + r * 68 + c0 + q * 8;
            float4 a = make_float4(s[0], s[1], s[2], s[3]);
            float4 bq = make_float4(s[4], s[5], s[6], s[7]);
            st_h8(dst + q * 8, a, bq);
        }
        __syncwarp();
    }
}

// ---------------------------------------------------------------------------
// Kernel 2: out[b] = W2[b] (512x512) @ Gr[b] (512x4096), fp16 WMMA.
// CUTLASS-shape: CTA 128(m) x 256(n), 256 thr / 8 warps (2m x 4n),
// warp tile 64x64, KT=32, 4-slot cp.async ring, one sync per chunk
// (prefetch issued after the barrier -> slot reuse is safe).
// ---------------------------------------------------------------------------
#define KTP   32
#define LDAPh 40
#define LDBPh 264
#define ASZh  (128 * LDAPh)
#define BSZh  (KTP * LDBPh)
#define STGh  (ASZh + BSZh)
#define NSTG  4

__global__ __launch_bounds__(256) void proj_kernel(float* __restrict__ outp)
{
    extern __shared__ __half psm[];

    const int b  = blockIdx.z;
    const int o0 = blockIdx.y * 128;
    const int n0 = blockIdx.x * 256;
    const __half* Ap = g_W2 + (size_t)b * NC * NC + (size_t)o0 * NC;
    const __half* Bp = g_Gr + (size_t)b * NC * NSP + n0;

    const int t    = threadIdx.x;
    const int warp = t >> 5;
    const int mw = (warp & 1) * 64;     // 0 or 64
    const int nw = (warp >> 1) * 64;    // 0,64,128,192

    // cp.async mappings (256 threads)
    const int ar = t >> 1,  aq = (t & 1) * 16;   // A: 128r x 32k halfs, 16/thr
    const int br = t >> 3,  bq = (t & 7) * 32;   // B: 32r x 256n halfs, 32/thr

    wmma::fragment<wmma::accumulator, 16, 16, 16, float> acc[4][4];
    #pragma unroll
    for (int i = 0; i < 4; ++i)
        #pragma unroll
        for (int j = 0; j < 4; ++j)
            wmma::fill_fragment(acc[i][j], 0.0f);

    const __half* agBase = Ap + (size_t)ar * NC + aq;
    const __half* bgBase = Bp + (size_t)br * NSP + bq;

    // prologue: chunks 0,1,2
    #pragma unroll
    for (int kc = 0; kc < 3; ++kc) {
        __half* sa = psm + kc * STGh;
        __half* sb = sa + ASZh;
        cp16(sa + ar * LDAPh + aq,     agBase + kc * KTP);
        cp16(sa + ar * LDAPh + aq + 8, agBase + kc * KTP + 8);
        #pragma unroll
        for (int j = 0; j < 4; ++j)
            cp16(sb + br * LDBPh + bq + j * 8, bgBase + (size_t)kc * KTP * NSP + j * 8);
        CP_COMMIT();
    }

    for (int kc = 0; kc < NC / KTP; ++kc) {
        CP_WAIT(2);            // 3 groups pending -> chunk kc complete
        __syncthreads();       // chunk kc visible; slot (kc+3)&3 reads all done

        const int kn = kc + 3;
        if (kn < NC / KTP) {
            __half* na = psm + (kn & 3) * STGh;
            __half* nb = na + ASZh;
            cp16(na + ar * LDAPh + aq,     agBase + kn * KTP);
            cp16(na + ar * LDAPh + aq + 8, agBase + kn * KTP + 8);
            #pragma unroll
            for (int j = 0; j < 4; ++j)
                cp16(nb + br * LDBPh + bq + j * 8, bgBase + (size_t)kn * KTP * NSP + j * 8);
        }
        CP_COMMIT();

        __half* sa = psm + (kc & 3) * STGh;
        __half* sb = sa + ASZh;

        #pragma unroll
        for (int kk = 0; kk < KTP; kk += 16) {
            wmma::fragment<wmma::matrix_b, 16, 16, 16, __half, wmma::row_major> bf[4];
            #pragma unroll
            for (int j = 0; j < 4; ++j)
                wmma::load_matrix_sync(bf[j], sb + kk * LDBPh + nw + j * 16, LDBPh);
            #pragma unroll
            for (int i = 0; i < 4; ++i) {
                wmma::fragment<wmma::matrix_a, 16, 16, 16, __half, wmma::row_major> af;
                wmma::load_matrix_sync(af, sa + (mw + i * 16) * LDAPh + kk, LDAPh);
                #pragma unroll
                for (int j = 0; j < 4; ++j)
                    wmma::mma_sync(acc[i][j], af, bf[j], acc[i][j]);
            }
        }
    }

    #pragma unroll
    for (int i = 0; i < 4; ++i)
        #pragma unroll
        for (int j = 0; j < 4; ++j)
            wmma::store_matrix_sync(
                outp + (size_t)(b * NC + o0 + mw + i * 16) * NSP + n0 + nw + j * 16,
                acc[i][j], NSP, wmma::mem_row_major);
}

extern "C" void kernel_launch(void* const* d_in, const int* in_sizes, int n_in,
                              void* d_out, int out_size) {
    (void)in_sizes; (void)n_in; (void)out_size;
    const float* localf  = (const float*)d_in[0];
    const float* globalf = (const float*)d_in[1];
    const float* temp    = (const float*)d_in[2];
    const float* projw   = (const float*)d_in[3];
    float* outp = (float*)d_out;

    cudaFuncSetAttribute(attn_partial_kernel, cudaFuncAttributeMaxDynamicSharedMemorySize,
                         PART_DSM);
    dim3 g1(2, NHEADS, NB);
    attn_partial_kernel<<<g1, 256, PART_DSM>>>(localf, globalf);

    dim3 g2(NHEADS, NB);
    attn_finalize_kernel<<<g2, 256>>>(temp, projw);

    cudaFuncSetAttribute(proj_kernel, cudaFuncAttributeMaxDynamicSharedMemorySize,
                         NSTG * STGh * (int)sizeof(__half));
    dim3 g3(NSP / 256, NC / 128, NB);
    proj_kernel<<<g3, 256, NSTG * STGh * sizeof(__half)>>>(outp);
}

// round 14
// speedup vs baseline: 1.0581x; 1.0581x over previous
#include <cuda_runtime.h>
#include <cuda_fp16.h>
#include <mma.h>
#include <cstdint>

using namespace nvcuda;

#define NB     32
#define NC     512
#define NHEADS 8
#define ND     64
#define NSP    4096   // H*W

// Scratch (no allocations allowed)
__device__ __half g_W2[(size_t)NB * NC * NC];          // fp16 W @ blockdiag(A)
__device__ __half g_Gr[(size_t)NB * NC * NSP];         // fp16-rounded G
__device__ float  g_Sp[(size_t)NB * NHEADS * 2 * ND * ND];  // partial Gram sums
__device__ float  g_sqp[(size_t)NB * NHEADS * 2 * 128];     // partial sumsq (L|G)

// ---------------------------------------------------------------------------
// helpers
// ---------------------------------------------------------------------------
__device__ __forceinline__ uint32_t smem_u32(const void* p) {
    uint32_t a;
    asm("{ .reg .u64 t; cvta.to.shared.u64 t, %1; cvt.u32.u64 %0, t; }" : "=r"(a) : "l"(p));
    return a;
}
__device__ __forceinline__ void cp16(void* dst_smem, const void* src) {
    asm volatile("cp.async.cg.shared.global [%0], [%1], 16;"
                 :: "r"(smem_u32(dst_smem)), "l"(src));
}
#define CP_COMMIT() asm volatile("cp.async.commit_group;" ::: "memory")
#define CP_WAIT(n)  asm volatile("cp.async.wait_group %0;" :: "n"(n) : "memory")

__device__ __forceinline__ void st_h8(__half* p, float4 a, float4 b) {
    union { __half2 h[4]; uint4 u; } pk;
    pk.h[0] = __floats2half2_rn(a.x, a.y);
    pk.h[1] = __floats2half2_rn(a.z, a.w);
    pk.h[2] = __floats2half2_rn(b.x, b.y);
    pk.h[3] = __floats2half2_rn(b.z, b.w);
    *(uint4*)p = pk.u;
}

// ---------------------------------------------------------------------------
// Kernel 1a: attn_partial.  grid (2, NHEADS, NB).  Each CTA: Gram + sumsq over
// cols [half*2048, +2048) via 4-slot cp.async raw ring; fp16 tiles; fp16 WMMA;
// writes partial S (fp32) and partial sumsq to global, fp16 G to g_Gr.
// ---------------------------------------------------------------------------
#define LDA1 36
#define RSTG (64 * LDA1 * 2)     // 4608 floats per raw stage
#define LDH1 40
#define PART_DSM (4 * RSTG * 4 + 2 * 64 * LDH1 * 2 * 2)
#define NHALF 2048
#define NCHK  (NHALF / 32)       // 64 chunks

__global__ __launch_bounds__(256) void attn_partial_kernel(
    const float* __restrict__ localf,
    const float* __restrict__ globalf)
{
    extern __shared__ char dsm[];
    float*  sRaw  = (float*)dsm;                         // 4 x 4608 floats
    __half* sHalf = (__half*)(dsm + 4 * RSTG * 4);       // 2 x 5120 halfs

    const int half = blockIdx.x;
    const int h    = blockIdx.y;
    const int b    = blockIdx.z;
    const int cbase = half * NHALF;
    const float* Lp = localf  + (size_t)(b * NC + h * ND) * NSP + cbase;
    const float* Gp = globalf + (size_t)(b * NC + h * ND) * NSP + cbase;

    const int t    = threadIdx.x;
    const int warp = t >> 5;
    const int srow = t >> 2;         // 0..63
    const int scol = (t & 3) * 8;    // 0,8,16,24

    const int m0 = (warp & 1) * 32;
    const int n0 = (warp >> 1) * 16;

    wmma::fragment<wmma::accumulator, 16, 16, 16, float> acc0, acc1;
    wmma::fill_fragment(acc0, 0.0f);
    wmma::fill_fragment(acc1, 0.0f);

    float sqL = 0.f, sqG = 0.f;

    const float* lsrc = Lp + (size_t)srow * NSP + scol;
    const float* gsrc = Gp + (size_t)srow * NSP + scol;
    const int rawOff = srow * LDA1 + scol;
    __half* grout = g_Gr + ((size_t)(b * NC + h * ND) + srow) * NSP + cbase + scol;

    #pragma unroll
    for (int kc = 0; kc < 3; ++kc) {
        float* dl = sRaw + kc * RSTG + rawOff;
        float* dg = dl + 64 * LDA1;
        cp16(dl, lsrc + kc * 32); cp16(dl + 4, lsrc + kc * 32 + 4);
        cp16(dg, gsrc + kc * 32); cp16(dg + 4, gsrc + kc * 32 + 4);
        CP_COMMIT();
    }

    for (int kc = 0; kc < NCHK; ++kc) {
        // slot (kc+3)&3 == (kc-1)&3; its raw reads finished before iter kc-1's
        // second barrier, which all threads passed before entering iter kc.
        const int kn = kc + 3;
        if (kn < NCHK) {
            float* dl = sRaw + (kn & 3) * RSTG + rawOff;
            float* dg = dl + 64 * LDA1;
            cp16(dl, lsrc + kn * 32); cp16(dl + 4, lsrc + kn * 32 + 4);
            cp16(dg, gsrc + kn * 32); cp16(dg + 4, gsrc + kn * 32 + 4);
        }
        CP_COMMIT();
        CP_WAIT(3);
        __syncthreads();

        float* stg = sRaw + (kc & 3) * RSTG;
        const float4* lp4 = (const float4*)(stg + rawOff);
        const float4* gp4 = (const float4*)(stg + 64 * LDA1 + rawOff);
        float4 l0 = lp4[0], l1 = lp4[1], g0 = gp4[0], g1 = gp4[1];

        sqL += l0.x*l0.x + l0.y*l0.y + l0.z*l0.z + l0.w*l0.w
             + l1.x*l1.x + l1.y*l1.y + l1.z*l1.z + l1.w*l1.w;
        sqG += g0.x*g0.x + g0.y*g0.y + g0.z*g0.z + g0.w*g0.w
             + g1.x*g1.x + g1.y*g1.y + g1.z*g1.z + g1.w*g1.w;

        __half* sLh = sHalf + (kc & 1) * 5120;
        __half* sGh = sLh + 64 * LDH1;
        st_h8(sLh + srow * LDH1 + scol, l0, l1);
        st_h8(sGh + srow * LDH1 + scol, g0, g1);
        st_h8(grout + kc * 32, g0, g1);
        __syncthreads();

        #pragma unroll
        for (int kk = 0; kk < 32; kk += 16) {
            wmma::fragment<wmma::matrix_b, 16, 16, 16, __half, wmma::col_major> bf;
            wmma::load_matrix_sync(bf, sGh + n0 * LDH1 + kk, LDH1);
            wmma::fragment<wmma::matrix_a, 16, 16, 16, __half, wmma::row_major> af;
            wmma::load_matrix_sync(af, sLh + m0 * LDH1 + kk, LDH1);
            wmma::mma_sync(acc0, af, bf, acc0);
            wmma::load_matrix_sync(af, sLh + (m0 + 16) * LDH1 + kk, LDH1);
            wmma::mma_sync(acc1, af, bf, acc1);
        }
    }

    // write partials
    const int bh2 = (b * NHEADS + h) * 2 + half;
    sqL += __shfl_xor_sync(0xffffffffu, sqL, 1);
    sqL += __shfl_xor_sync(0xffffffffu, sqL, 2);
    sqG += __shfl_xor_sync(0xffffffffu, sqG, 1);
    sqG += __shfl_xor_sync(0xffffffffu, sqG, 2);
    if ((t & 3) == 0) {
        g_sqp[(size_t)bh2 * 128 + srow]      = sqL;
        g_sqp[(size_t)bh2 * 128 + 64 + srow] = sqG;
    }
    float* sp = g_Sp + (size_t)bh2 * ND * ND;
    wmma::store_matrix_sync(sp + m0 * ND + n0, acc0, ND, wmma::mem_row_major);
    wmma::store_matrix_sync(sp + (m0 + 16) * ND + n0, acc1, ND, wmma::mem_row_major);
}

// ---------------------------------------------------------------------------
// Kernel 1b: attn_finalize.  grid (NHEADS, NB).  S = S0+S1; fp32 softmax ->
// fp16 A; W2 slice = W[:,h*64:+64] @ A -> fp16 g_W2.  Static smem.
// ---------------------------------------------------------------------------
#define LDS1 68
#define LDSH 72

__global__ __launch_bounds__(256) void attn_finalize_kernel(
    const float* __restrict__ temp,
    const float* __restrict__ projw)
{
    __shared__ float sBuf[10880];            // 43.5 KB static
    float*  sS  = sBuf;                      // 64x68 f32        (4352 f)
    __half* sSh = (__half*)(sBuf + 4352);    // 64x72 h          (2304 f)
    __half* sWp = (__half*)(sBuf + 4352 + 2304);  // 512x16 h    (4096 f)
    float*  sInv = sBuf + 4352 + 2304 + 4096;     // 128 f

    const int h = blockIdx.x;
    const int b = blockIdx.y;
    const int t    = threadIdx.x;
    const int lane = t & 31;
    const int warp = t >> 5;

    const int bh = b * NHEADS + h;
    const float* sp0 = g_Sp + (size_t)(bh * 2)     * ND * ND;
    const float* sp1 = g_Sp + (size_t)(bh * 2 + 1) * ND * ND;

    for (int i = t; i < ND * ND; i += 256) {
        sS[(i >> 6) * LDS1 + (i & 63)] = sp0[i] + sp1[i];
    }
    if (t < 128) {
        float sq = g_sqp[(size_t)(bh * 2) * 128 + t] + g_sqp[(size_t)(bh * 2 + 1) * 128 + t];
        sInv[t] = 1.f / fmaxf(sqrtf(sq), 1e-12f);
    }
    __syncthreads();

    const float tval = temp[h];
    for (int rr = warp * 8; rr < warp * 8 + 8; ++rr) {
        float il = sInv[rr] * tval;
        float x1 = sS[rr * LDS1 + lane]      * il * sInv[64 + lane];
        float x2 = sS[rr * LDS1 + 32 + lane] * il * sInv[96 + lane];
        float mx = fmaxf(x1, x2);
        #pragma unroll
        for (int o = 16; o > 0; o >>= 1)
            mx = fmaxf(mx, __shfl_xor_sync(0xffffffffu, mx, o));
        float e1 = expf(x1 - mx);
        float e2 = expf(x2 - mx);
        float s = e1 + e2;
        #pragma unroll
        for (int o = 16; o > 0; o >>= 1)
            s += __shfl_xor_sync(0xffffffffu, s, o);
        float is = 1.f / s;
        sSh[rr * LDSH + lane]      = __float2half_rn(e1 * is);
        sSh[rr * LDSH + 32 + lane] = __float2half_rn(e2 * is);
    }
    __syncthreads();

    // Phase C: W2 slice [512 x 64] = W[:, h*64:+64] @ A
    const int o0w = warp * 64;
    const int hk  = h * ND;
    wmma::fragment<wmma::accumulator, 16, 16, 16, float> wacc[4][4];
    #pragma unroll
    for (int i = 0; i < 4; ++i)
        #pragma unroll
        for (int j = 0; j < 4; ++j)
            wmma::fill_fragment(wacc[i][j], 0.0f);

    for (int kg = 0; kg < 4; ++kg) {
        for (int idx = t; idx < 512 * 4; idx += 256) {
            const int o = idx >> 2, q = (idx & 3) * 4;
            float4 wv = *(const float4*)(projw + (size_t)o * NC + hk + kg * 16 + q);
            __half* d = sWp + o * 16 + q;
            d[0] = __float2half_rn(wv.x); d[1] = __float2half_rn(wv.y);
            d[2] = __float2half_rn(wv.z); d[3] = __float2half_rn(wv.w);
        }
        __syncthreads();

        wmma::fragment<wmma::matrix_b, 16, 16, 16, __half, wmma::row_major> bf[4];
        #pragma unroll
        for (int j = 0; j < 4; ++j)
            wmma::load_matrix_sync(bf[j], sSh + (kg * 16) * LDSH + j * 16, LDSH);
        #pragma unroll
        for (int i = 0; i < 4; ++i) {
            wmma::fragment<wmma::matrix_a, 16, 16, 16, __half, wmma::row_major> af;
            wmma::load_matrix_sync(af, sWp + (o0w + i * 16) * 16, 16);
            #pragma unroll
            for (int j = 0; j < 4; ++j)
                wmma::mma_sync(wacc[i][j], af, bf[j], wacc[i][j]);
        }
        __syncthreads();
    }

    // write W2 slice as fp16 via per-warp fp32 scratch (reuse sBuf; all prior
    // smem users are dead and fenced by the barrier above)
    float* sW = sBuf + warp * 1088;     // 16x68 slab per warp (8*1088=8704<=10880)
    __half* w2p = g_W2 + (size_t)b * NC * NC;
    const int r  = lane >> 1;
    const int c0 = (lane & 1) * 32;
    #pragma unroll
    for (int i = 0; i < 4; ++i) {
        #pragma unroll
        for (int j = 0; j < 4; ++j)
            wmma::store_matrix_sync(sW + j * 16, wacc[i][j], 68, wmma::mem_row_major);
        __syncwarp();
        __half* dst = w2p + (size_t)(o0w + i * 16 + r) * NC + hk + c0;
        #pragma unroll
        for (int q = 0; q < 4; ++q) {
            const float* s = sW + r * 68 + c0 + q * 8;
            float4 a = make_float4(s[0], s[1], s[2], s[3]);
            float4 bq = make_float4(s[4], s[5], s[6], s[7]);
            st_h8(dst + q * 8, a, bq);
        }
        __syncwarp();
    }
}

// ---------------------------------------------------------------------------
// Kernel 2: out[b] = W2[b] (512x512) @ Gr[b] (512x4096), fp16 WMMA.
// R12-proven config: CTA 128(m) x 256(n), 512 thr / 16 warps (2m x 8n),
// warp tile 64x32, KT=32, 4-slot cp.async ring, one sync per chunk
// (prefetch issued after the barrier -> slot reuse is safe).
// ---------------------------------------------------------------------------
#define KTP   32
#define LDAPh 40
#define LDBPh 264
#define ASZh  (128 * LDAPh)
#define BSZh  (KTP * LDBPh)
#define STGh  (ASZh + BSZh)
#define NSTG  4

__global__ __launch_bounds__(512) void proj_kernel(float* __restrict__ outp)
{
    extern __shared__ __half psm[];

    const int b  = blockIdx.z;
    const int o0 = blockIdx.y * 128;
    const int n0 = blockIdx.x * 256;
    const __half* Ap = g_W2 + (size_t)b * NC * NC + (size_t)o0 * NC;
    const __half* Bp = g_Gr + (size_t)b * NC * NSP + n0;

    const int t    = threadIdx.x;
    const int warp = t >> 5;
    const int mw = (warp & 1) * 64;     // 0 or 64
    const int nw = (warp >> 1) * 32;    // 0..224

    // cp.async mappings (512 threads)
    const int ar = t >> 2,  aq = (t & 3) * 8;    // A: 128r x 32k halfs, 8/thr
    const int br = t >> 4,  bq = (t & 15) * 16;  // B: 32r x 256n halfs, 16/thr

    wmma::fragment<wmma::accumulator, 16, 16, 16, float> acc[4][2];
    #pragma unroll
    for (int i = 0; i < 4; ++i)
        #pragma unroll
        for (int j = 0; j < 2; ++j)
            wmma::fill_fragment(acc[i][j], 0.0f);

    const __half* agBase = Ap + (size_t)ar * NC + aq;
    const __half* bgBase = Bp + (size_t)br * NSP + bq;

    // prologue: chunks 0,1,2
    #pragma unroll
    for (int kc = 0; kc < 3; ++kc) {
        __half* sa = psm + kc * STGh;
        __half* sb = sa + ASZh;
        cp16(sa + ar * LDAPh + aq, agBase + kc * KTP);
        cp16(sb + br * LDBPh + bq,     bgBase + (size_t)kc * KTP * NSP);
        cp16(sb + br * LDBPh + bq + 8, bgBase + (size_t)kc * KTP * NSP + 8);
        CP_COMMIT();
    }

    for (int kc = 0; kc < NC / KTP; ++kc) {
        CP_WAIT(2);            // 3 groups pending -> chunk kc complete
        __syncthreads();       // chunk kc visible; slot (kc+3)&3 reads all done

        const int kn = kc + 3;
        if (kn < NC / KTP) {
            __half* na = psm + (kn & 3) * STGh;
            __half* nb = na + ASZh;
            cp16(na + ar * LDAPh + aq, agBase + kn * KTP);
            cp16(nb + br * LDBPh + bq,     bgBase + (size_t)kn * KTP * NSP);
            cp16(nb + br * LDBPh + bq + 8, bgBase + (size_t)kn * KTP * NSP + 8);
        }
        CP_COMMIT();

        __half* sa = psm + (kc & 3) * STGh;
        __half* sb = sa + ASZh;

        #pragma unroll
        for (int kk = 0; kk < KTP; kk += 16) {
            wmma::fragment<wmma::matrix_b, 16, 16, 16, __half, wmma::row_major> bf[2];
            #pragma unroll
            for (int j = 0; j < 2; ++j)
                wmma::load_matrix_sync(bf[j], sb + kk * LDBPh + nw + j * 16, LDBPh);
            #pragma unroll
            for (int i = 0; i < 4; ++i) {
                wmma::fragment<wmma::matrix_a, 16, 16, 16, __half, wmma::row_major> af;
                wmma::load_matrix_sync(af, sa + (mw + i * 16) * LDAPh + kk, LDAPh);
                #pragma unroll
                for (int j = 0; j < 2; ++j)
                    wmma::mma_sync(acc[i][j], af, bf[j], acc[i][j]);
            }
        }
    }

    #pragma unroll
    for (int i = 0; i < 4; ++i)
        #pragma unroll
        for (int j = 0; j < 2; ++j)
            wmma::store_matrix_sync(
                outp + (size_t)(b * NC + o0 + mw + i * 16) * NSP + n0 + nw + j * 16,
                acc[i][j], NSP, wmma::mem_row_major);
}

extern "C" void kernel_launch(void* const* d_in, const int* in_sizes, int n_in,
                              void* d_out, int out_size) {
    (void)in_sizes; (void)n_in; (void)out_size;
    const float* localf  = (const float*)d_in[0];
    const float* globalf = (const float*)d_in[1];
    const float* temp    = (const float*)d_in[2];
    const float* projw   = (const float*)d_in[3];
    float* outp = (float*)d_out;

    cudaFuncSetAttribute(attn_partial_kernel, cudaFuncAttributeMaxDynamicSharedMemorySize,
                         PART_DSM);
    dim3 g1(2, NHEADS, NB);
    attn_partial_kernel<<<g1, 256, PART_DSM>>>(localf, globalf);

    dim3 g2(NHEADS, NB);
    attn_finalize_kernel<<<g2, 256>>>(temp, projw);

    cudaFuncSetAttribute(proj_kernel, cudaFuncAttributeMaxDynamicSharedMemorySize,
                         NSTG * STGh * (int)sizeof(__half));
    dim3 g3(NSP / 256, NC / 128, NB);
    proj_kernel<<<g3, 512, NSTG * STGh * sizeof(__half)>>>(outp);
}

// round 15
// speedup vs baseline: 1.1516x; 1.0883x over previous
#include <cuda_runtime.h>
#include <cuda_fp16.h>
#include <mma.h>
#include <cstdint>

using namespace nvcuda;

#define NB     32
#define NC     512
#define NHEADS 8
#define ND     64
#define NSP    4096   // H*W
#define NQ     4      // attn split factor

// Scratch (no allocations allowed)
__device__ __half g_W2[(size_t)NB * NC * NC];          // fp16 W @ blockdiag(A)
__device__ __half g_Gr[(size_t)NB * NC * NSP];         // fp16-rounded G
__device__ float  g_Sp[(size_t)NB * NHEADS * NQ * ND * ND];  // partial Gram sums
__device__ float  g_sqp[(size_t)NB * NHEADS * NQ * 128];     // partial sumsq (L|G)

// ---------------------------------------------------------------------------
// helpers
// ---------------------------------------------------------------------------
__device__ __forceinline__ uint32_t smem_u32(const void* p) {
    uint32_t a;
    asm("{ .reg .u64 t; cvta.to.shared.u64 t, %1; cvt.u32.u64 %0, t; }" : "=r"(a) : "l"(p));
    return a;
}
__device__ __forceinline__ void cp16(void* dst_smem, const void* src) {
    asm volatile("cp.async.cg.shared.global [%0], [%1], 16;"
                 :: "r"(smem_u32(dst_smem)), "l"(src));
}
#define CP_COMMIT() asm volatile("cp.async.commit_group;" ::: "memory")
#define CP_WAIT(n)  asm volatile("cp.async.wait_group %0;" :: "n"(n) : "memory")

__device__ __forceinline__ void st_h8(__half* p, float4 a, float4 b) {
    union { __half2 h[4]; uint4 u; } pk;
    pk.h[0] = __floats2half2_rn(a.x, a.y);
    pk.h[1] = __floats2half2_rn(a.z, a.w);
    pk.h[2] = __floats2half2_rn(b.x, b.y);
    pk.h[3] = __floats2half2_rn(b.z, b.w);
    *(uint4*)p = pk.u;
}

// ---------------------------------------------------------------------------
// Kernel 1a: attn_partial.  grid (NQ, NHEADS, NB).  Each CTA: Gram + sumsq
// over cols [q*1024, +1024) via 4-slot cp.async raw ring; fp16 tiles; fp16
// WMMA; writes partial S (fp32), partial sumsq, and fp16 G to g_Gr.
// ---------------------------------------------------------------------------
#define LDA1 36
#define RSTG (64 * LDA1 * 2)     // 4608 floats per raw stage
#define LDH1 40
#define PART_DSM (4 * RSTG * 4 + 2 * 64 * LDH1 * 2 * 2)
#define NQCOL (NSP / NQ)         // 1024
#define NCHK  (NQCOL / 32)       // 32 chunks

__global__ __launch_bounds__(256) void attn_partial_kernel(
    const float* __restrict__ localf,
    const float* __restrict__ globalf)
{
    extern __shared__ char dsm[];
    float*  sRaw  = (float*)dsm;                         // 4 x 4608 floats
    __half* sHalf = (__half*)(dsm + 4 * RSTG * 4);       // 2 x 5120 halfs

    const int q = blockIdx.x;
    const int h = blockIdx.y;
    const int b = blockIdx.z;
    const int cbase = q * NQCOL;
    const float* Lp = localf  + (size_t)(b * NC + h * ND) * NSP + cbase;
    const float* Gp = globalf + (size_t)(b * NC + h * ND) * NSP + cbase;

    const int t    = threadIdx.x;
    const int warp = t >> 5;
    const int srow = t >> 2;         // 0..63
    const int scol = (t & 3) * 8;    // 0,8,16,24

    const int m0 = (warp & 1) * 32;
    const int n0 = (warp >> 1) * 16;

    wmma::fragment<wmma::accumulator, 16, 16, 16, float> acc0, acc1;
    wmma::fill_fragment(acc0, 0.0f);
    wmma::fill_fragment(acc1, 0.0f);

    float sqL = 0.f, sqG = 0.f;

    const float* lsrc = Lp + (size_t)srow * NSP + scol;
    const float* gsrc = Gp + (size_t)srow * NSP + scol;
    const int rawOff = srow * LDA1 + scol;
    __half* grout = g_Gr + ((size_t)(b * NC + h * ND) + srow) * NSP + cbase + scol;

    #pragma unroll
    for (int kc = 0; kc < 3; ++kc) {
        float* dl = sRaw + kc * RSTG + rawOff;
        float* dg = dl + 64 * LDA1;
        cp16(dl, lsrc + kc * 32); cp16(dl + 4, lsrc + kc * 32 + 4);
        cp16(dg, gsrc + kc * 32); cp16(dg + 4, gsrc + kc * 32 + 4);
        CP_COMMIT();
    }

    for (int kc = 0; kc < NCHK; ++kc) {
        // slot (kc+3)&3 == (kc-1)&3; its raw reads finished before iter kc-1's
        // second barrier, which all threads passed before entering iter kc.
        const int kn = kc + 3;
        if (kn < NCHK) {
            float* dl = sRaw + (kn & 3) * RSTG + rawOff;
            float* dg = dl + 64 * LDA1;
            cp16(dl, lsrc + kn * 32); cp16(dl + 4, lsrc + kn * 32 + 4);
            cp16(dg, gsrc + kn * 32); cp16(dg + 4, gsrc + kn * 32 + 4);
        }
        CP_COMMIT();
        CP_WAIT(3);
        __syncthreads();

        float* stg = sRaw + (kc & 3) * RSTG;
        const float4* lp4 = (const float4*)(stg + rawOff);
        const float4* gp4 = (const float4*)(stg + 64 * LDA1 + rawOff);
        float4 l0 = lp4[0], l1 = lp4[1], g0 = gp4[0], g1 = gp4[1];

        sqL += l0.x*l0.x + l0.y*l0.y + l0.z*l0.z + l0.w*l0.w
             + l1.x*l1.x + l1.y*l1.y + l1.z*l1.z + l1.w*l1.w;
        sqG += g0.x*g0.x + g0.y*g0.y + g0.z*g0.z + g0.w*g0.w
             + g1.x*g1.x + g1.y*g1.y + g1.z*g1.z + g1.w*g1.w;

        __half* sLh = sHalf + (kc & 1) * 5120;
        __half* sGh = sLh + 64 * LDH1;
        st_h8(sLh + srow * LDH1 + scol, l0, l1);
        st_h8(sGh + srow * LDH1 + scol, g0, g1);
        st_h8(grout + kc * 32, g0, g1);
        __syncthreads();

        #pragma unroll
        for (int kk = 0; kk < 32; kk += 16) {
            wmma::fragment<wmma::matrix_b, 16, 16, 16, __half, wmma::col_major> bf;
            wmma::load_matrix_sync(bf, sGh + n0 * LDH1 + kk, LDH1);
            wmma::fragment<wmma::matrix_a, 16, 16, 16, __half, wmma::row_major> af;
            wmma::load_matrix_sync(af, sLh + m0 * LDH1 + kk, LDH1);
            wmma::mma_sync(acc0, af, bf, acc0);
            wmma::load_matrix_sync(af, sLh + (m0 + 16) * LDH1 + kk, LDH1);
            wmma::mma_sync(acc1, af, bf, acc1);
        }
    }

    // write partials
    const int bhq = (b * NHEADS + h) * NQ + q;
    sqL += __shfl_xor_sync(0xffffffffu, sqL, 1);
    sqL += __shfl_xor_sync(0xffffffffu, sqL, 2);
    sqG += __shfl_xor_sync(0xffffffffu, sqG, 1);
    sqG += __shfl_xor_sync(0xffffffffu, sqG, 2);
    if ((t & 3) == 0) {
        g_sqp[(size_t)bhq * 128 + srow]      = sqL;
        g_sqp[(size_t)bhq * 128 + 64 + srow] = sqG;
    }
    float* sp = g_Sp + (size_t)bhq * ND * ND;
    wmma::store_matrix_sync(sp + m0 * ND + n0, acc0, ND, wmma::mem_row_major);
    wmma::store_matrix_sync(sp + (m0 + 16) * ND + n0, acc1, ND, wmma::mem_row_major);
}

// ---------------------------------------------------------------------------
// Kernel 1b: attn_finalize.  grid (NHEADS, NB).  S = sum of NQ partials;
// fp32 softmax -> fp16 A; W2 slice = W[:,h*64:+64] @ A -> fp16 g_W2.
// ---------------------------------------------------------------------------
#define LDS1 68
#define LDSH 72

__global__ __launch_bounds__(256) void attn_finalize_kernel(
    const float* __restrict__ temp,
    const float* __restrict__ projw)
{
    __shared__ float sBuf[10880];            // 43.5 KB static
    float*  sS  = sBuf;                      // 64x68 f32        (4352 f)
    __half* sSh = (__half*)(sBuf + 4352);    // 64x72 h          (2304 f)
    __half* sWp = (__half*)(sBuf + 4352 + 2304);  // 512x16 h    (4096 f)
    float*  sInv = sBuf + 4352 + 2304 + 4096;     // 128 f

    const int h = blockIdx.x;
    const int b = blockIdx.y;
    const int t    = threadIdx.x;
    const int lane = t & 31;
    const int warp = t >> 5;

    const int bh = b * NHEADS + h;
    const float* sp = g_Sp + (size_t)(bh * NQ) * ND * ND;

    for (int i = t; i < ND * ND; i += 256) {
        float v = sp[i] + sp[ND * ND + i] + sp[2 * ND * ND + i] + sp[3 * ND * ND + i];
        sS[(i >> 6) * LDS1 + (i & 63)] = v;
    }
    if (t < 128) {
        const float* qp = g_sqp + (size_t)(bh * NQ) * 128;
        float sq = qp[t] + qp[128 + t] + qp[256 + t] + qp[384 + t];
        sInv[t] = 1.f / fmaxf(sqrtf(sq), 1e-12f);
    }
    __syncthreads();

    const float tval = temp[h];
    for (int rr = warp * 8; rr < warp * 8 + 8; ++rr) {
        float il = sInv[rr] * tval;
        float x1 = sS[rr * LDS1 + lane]      * il * sInv[64 + lane];
        float x2 = sS[rr * LDS1 + 32 + lane] * il * sInv[96 + lane];
        float mx = fmaxf(x1, x2);
        #pragma unroll
        for (int o = 16; o > 0; o >>= 1)
            mx = fmaxf(mx, __shfl_xor_sync(0xffffffffu, mx, o));
        float e1 = expf(x1 - mx);
        float e2 = expf(x2 - mx);
        float s = e1 + e2;
        #pragma unroll
        for (int o = 16; o > 0; o >>= 1)
            s += __shfl_xor_sync(0xffffffffu, s, o);
        float is = 1.f / s;
        sSh[rr * LDSH + lane]      = __float2half_rn(e1 * is);
        sSh[rr * LDSH + 32 + lane] = __float2half_rn(e2 * is);
    }
    __syncthreads();

    // Phase C: W2 slice [512 x 64] = W[:, h*64:+64] @ A
    const int o0w = warp * 64;
    const int hk  = h * ND;
    wmma::fragment<wmma::accumulator, 16, 16, 16, float> wacc[4][4];
    #pragma unroll
    for (int i = 0; i < 4; ++i)
        #pragma unroll
        for (int j = 0; j < 4; ++j)
            wmma::fill_fragment(wacc[i][j], 0.0f);

    for (int kg = 0; kg < 4; ++kg) {
        for (int idx = t; idx < 512 * 4; idx += 256) {
            const int o = idx >> 2, qx = (idx & 3) * 4;
            float4 wv = *(const float4*)(projw + (size_t)o * NC + hk + kg * 16 + qx);
            __half* d = sWp + o * 16 + qx;
            d[0] = __float2half_rn(wv.x); d[1] = __float2half_rn(wv.y);
            d[2] = __float2half_rn(wv.z); d[3] = __float2half_rn(wv.w);
        }
        __syncthreads();

        wmma::fragment<wmma::matrix_b, 16, 16, 16, __half, wmma::row_major> bf[4];
        #pragma unroll
        for (int j = 0; j < 4; ++j)
            wmma::load_matrix_sync(bf[j], sSh + (kg * 16) * LDSH + j * 16, LDSH);
        #pragma unroll
        for (int i = 0; i < 4; ++i) {
            wmma::fragment<wmma::matrix_a, 16, 16, 16, __half, wmma::row_major> af;
            wmma::load_matrix_sync(af, sWp + (o0w + i * 16) * 16, 16);
            #pragma unroll
            for (int j = 0; j < 4; ++j)
                wmma::mma_sync(wacc[i][j], af, bf[j], wacc[i][j]);
        }
        __syncthreads();
    }

    // write W2 slice as fp16 via per-warp fp32 scratch (smem reuse is fenced)
    float* sW = sBuf + warp * 1088;     // 16x68 slab per warp
    __half* w2p = g_W2 + (size_t)b * NC * NC;
    const int r  = lane >> 1;
    const int c0 = (lane & 1) * 32;
    #pragma unroll
    for (int i = 0; i < 4; ++i) {
        #pragma unroll
        for (int j = 0; j < 4; ++j)
            wmma::store_matrix_sync(sW + j * 16, wacc[i][j], 68, wmma::mem_row_major);
        __syncwarp();
        __half* dst = w2p + (size_t)(o0w + i * 16 + r) * NC + hk + c0;
        #pragma unroll
        for (int qx = 0; qx < 4; ++qx) {
            const float* s = sW + r * 68 + c0 + qx * 8;
            float4 a = make_float4(s[0], s[1], s[2], s[3]);
            float4 bq = make_float4(s[4], s[5], s[6], s[7]);
            st_h8(dst + qx * 8, a, bq);
        }
        __syncwarp();
    }
}

// ---------------------------------------------------------------------------
// Kernel 2: out[b] = W2[b] (512x512) @ Gr[b] (512x4096), fp16 WMMA.
// CTA 128(m) x 128(n), 256 thr / 8 warps (2m x 4n), warp tile 64x32, KT=32,
// 4-slot cp.async ring, one sync per chunk (prefetch after barrier).
// __launch_bounds__(256, 2): TWO CTAs per SM so barrier/wait stalls of one
// CTA are hidden by the other's MMA work.
// ---------------------------------------------------------------------------
#define KTP   32
#define LDAPh 40                  // 128 x 32 A tile ld (halfs)
#define LDBPh 136                 // 32 x 128 B tile ld (halfs)
#define ASZh  (128 * LDAPh)       // 5120 halfs
#define BSZh  (KTP * LDBPh)       // 4352 halfs
#define STGh  (ASZh + BSZh)       // 9472 halfs = 18944 B
#define NSTG  4                   // 75776 B per CTA

__global__ __launch_bounds__(256, 2) void proj_kernel(float* __restrict__ outp)
{
    extern __shared__ __half psm[];

    const int b  = blockIdx.z;
    const int o0 = blockIdx.y * 128;
    const int n0 = blockIdx.x * 128;
    const __half* Ap = g_W2 + (size_t)b * NC * NC + (size_t)o0 * NC;
    const __half* Bp = g_Gr + (size_t)b * NC * NSP + n0;

    const int t    = threadIdx.x;
    const int warp = t >> 5;
    const int mw = (warp & 1) * 64;     // 0 or 64
    const int nw = (warp >> 1) * 32;    // 0,32,64,96

    // cp.async mappings (256 threads)
    const int ar = t >> 1,  aq = (t & 1) * 16;   // A: 128r x 32k halfs, 16/thr
    const int br = t >> 3,  bq = (t & 7) * 16;   // B: 32r x 128n halfs, 16/thr

    wmma::fragment<wmma::accumulator, 16, 16, 16, float> acc[4][2];
    #pragma unroll
    for (int i = 0; i < 4; ++i)
        #pragma unroll
        for (int j = 0; j < 2; ++j)
            wmma::fill_fragment(acc[i][j], 0.0f);

    const __half* agBase = Ap + (size_t)ar * NC + aq;
    const __half* bgBase = Bp + (size_t)br * NSP + bq;

    // prologue: chunks 0,1,2
    #pragma unroll
    for (int kc = 0; kc < 3; ++kc) {
        __half* sa = psm + kc * STGh;
        __half* sb = sa + ASZh;
        cp16(sa + ar * LDAPh + aq,     agBase + kc * KTP);
        cp16(sa + ar * LDAPh + aq + 8, agBase + kc * KTP + 8);
        cp16(sb + br * LDBPh + bq,     bgBase + (size_t)kc * KTP * NSP);
        cp16(sb + br * LDBPh + bq + 8, bgBase + (size_t)kc * KTP * NSP + 8);
        CP_COMMIT();
    }

    for (int kc = 0; kc < NC / KTP; ++kc) {
        CP_WAIT(2);            // 3 groups pending -> chunk kc complete
        __syncthreads();       // chunk kc visible; slot (kc+3)&3 reads all done

        const int kn = kc + 3;
        if (kn < NC / KTP) {
            __half* na = psm + (kn & 3) * STGh;
            __half* nb = na + ASZh;
            cp16(na + ar * LDAPh + aq,     agBase + kn * KTP);
            cp16(na + ar * LDAPh + aq + 8, agBase + kn * KTP + 8);
            cp16(nb + br * LDBPh + bq,     bgBase + (size_t)kn * KTP * NSP);
            cp16(nb + br * LDBPh + bq + 8, bgBase + (size_t)kn * KTP * NSP + 8);
        }
        CP_COMMIT();

        __half* sa = psm + (kc & 3) * STGh;
        __half* sb = sa + ASZh;

        #pragma unroll
        for (int kk = 0; kk < KTP; kk += 16) {
            wmma::fragment<wmma::matrix_b, 16, 16, 16, __half, wmma::row_major> bf[2];
            #pragma unroll
            for (int j = 0; j < 2; ++j)
                wmma::load_matrix_sync(bf[j], sb + kk * LDBPh + nw + j * 16, LDBPh);
            #pragma unroll
            for (int i = 0; i < 4; ++i) {
                wmma::fragment<wmma::matrix_a, 16, 16, 16, __half, wmma::row_major> af;
                wmma::load_matrix_sync(af, sa + (mw + i * 16) * LDAPh + kk, LDAPh);
                #pragma unroll
                for (int j = 0; j < 2; ++j)
                    wmma::mma_sync(acc[i][j], af, bf[j], acc[i][j]);
            }
        }
    }

    #pragma unroll
    for (int i = 0; i < 4; ++i)
        #pragma unroll
        for (int j = 0; j < 2; ++j)
            wmma::store_matrix_sync(
                outp + (size_t)(b * NC + o0 + mw + i * 16) * NSP + n0 + nw + j * 16,
                acc[i][j], NSP, wmma::mem_row_major);
}

extern "C" void kernel_launch(void* const* d_in, const int* in_sizes, int n_in,
                              void* d_out, int out_size) {
    (void)in_sizes; (void)n_in; (void)out_size;
    const float* localf  = (const float*)d_in[0];
    const float* globalf = (const float*)d_in[1];
    const float* temp    = (const float*)d_in[2];
    const float* projw   = (const float*)d_in[3];
    float* outp = (float*)d_out;

    cudaFuncSetAttribute(attn_partial_kernel, cudaFuncAttributeMaxDynamicSharedMemorySize,
                         PART_DSM);
    dim3 g1(NQ, NHEADS, NB);
    attn_partial_kernel<<<g1, 256, PART_DSM>>>(localf, globalf);

    dim3 g2(NHEADS, NB);
    attn_finalize_kernel<<<g2, 256>>>(temp, projw);

    cudaFuncSetAttribute(proj_kernel, cudaFuncAttributeMaxDynamicSharedMemorySize,
                         NSTG * STGh * (int)sizeof(__half));
    dim3 g3(NSP / 128, NC / 128, NB);
    proj_kernel<<<g3, 256, NSTG * STGh * sizeof(__half)>>>(outp);
}